// round 16
// baseline (speedup 1.0000x reference)
#include <cuda_runtime.h>
#include <cuda_fp16.h>

// Problem constants (fixed by the dataset)
#define NMAX 50048
#define EMAX 1600000
#define WDIM 64
#define HDIM 128

// Scratch (allocation-free rule: __device__ globals)
__device__ __half gA[NMAX * HDIM];     // x @ w1[0:64,:]  + b1
__device__ __half gB[NMAX * HDIM];     // x @ w1[64:128,:]
__device__ int    gCnt[NMAX];          // per-dst edge count (self-cleaning:
                                       // zero at load; fused_node re-zeros)
__device__ int    gOff[NMAX + 1];      // exclusive prefix (bin starts)
__device__ int    gCursor[NMAX];       // scatter cursors
__device__ int2   gSortedE[EMAX];      // {src, orig_e} grouped by dst
__device__ float  gEsort[EMAX];        // exp(logit) in sorted order
// lookback scan state (flags reset each call before the first grid barrier)
__device__ volatile int gBlockSum[256];
__device__ volatile int gBlockFlag[256];
// sense-reversing grid barrier state (self-resetting => replay-safe)
__device__ int          gBarCnt = 0;
__device__ volatile int gBarSense = 0;

#define TR 16
#define PREP_BLOCKS 444   // 3 blocks/SM x 148 SMs: co-resident by construction

// ---------------------------------------------------------------------------
// Grid-wide barrier for a co-resident grid. Sense-reversing, self-resetting.
// ---------------------------------------------------------------------------
__device__ __forceinline__ void grid_barrier(int nblocks) {
    __syncthreads();
    if (threadIdx.x == 0) {
        int s = gBarSense;                 // capture sense BEFORE arriving
        __threadfence();                   // publish this block's writes
        if (atomicAdd(&gBarCnt, 1) == nblocks - 1) {
            gBarCnt = 0;                   // reset for next barrier/replay
            __threadfence();
            gBarSense = s ^ 1;             // release
        } else {
            while (gBarSense == s) { }
            __threadfence();               // acquire released writes
        }
    }
    __syncthreads();
}

// ---------------------------------------------------------------------------
// Kernel 1 (persistent prep): precompute A/B + histogram -> barrier ->
// lookback scan -> barrier -> scatter. One launch replaces three.
// ---------------------------------------------------------------------------
__global__ void __launch_bounds__(256, 3) prep_kernel(
        const float* __restrict__ x,
        const float* __restrict__ w1,
        const float* __restrict__ b1,
        const int* __restrict__ src,
        const int* __restrict__ dst,
        int N, int E, int Ptiles) {
    __shared__ float xs[TR][WDIM];
    __shared__ int   sh[256];
    __shared__ int   pre[256];
    const int tid = threadIdx.x;

    // reset scan flags for this invocation (visible after barrier 1)
    if (blockIdx.x == 0) gBlockFlag[tid] = 0;

    // ---- P0a: per-node precompute, grid-stride over row tiles ----
    for (int tile = blockIdx.x; tile < Ptiles; tile += gridDim.x) {
        const int row0 = tile * TR;
        for (int i = tid; i < TR * WDIM; i += 256) {
            int r = i >> 6, k = i & 63;
            int gr = row0 + r;
            xs[r][k] = (gr < N) ? x[gr * WDIM + k] : 0.0f;
        }
        __syncthreads();

        const int col  = tid & 127;
        const int half = tid >> 7;   // 0 -> A, 1 -> B
        const float* wbase = w1 + half * WDIM * HDIM + col;

        float acc[TR];
#pragma unroll
        for (int r = 0; r < TR; r++) acc[r] = 0.0f;
#pragma unroll 8
        for (int k = 0; k < WDIM; k++) {
            float w = __ldg(wbase + k * HDIM);
#pragma unroll
            for (int r = 0; r < TR; r++) acc[r] += xs[r][k] * w;
        }

        const float bias = (half == 0) ? __ldg(&b1[col]) : 0.0f;
        __half* out = (half == 0) ? gA : gB;
#pragma unroll
        for (int r = 0; r < TR; r++) {
            int gr = row0 + r;
            if (gr < N) out[gr * HDIM + col] = __float2half_rn(acc[r] + bias);
        }
        __syncthreads();   // protect xs before next tile's fill
    }

    // ---- P0b: dst histogram, grid-stride, 4 edges/step (RED, no return) ----
    const int nquads = E >> 2;
    for (int t = blockIdx.x * 256 + tid; t < nquads; t += gridDim.x * 256) {
        int4 d4 = reinterpret_cast<const int4*>(dst)[t];
        atomicAdd(&gCnt[d4.x], 1);
        atomicAdd(&gCnt[d4.y], 1);
        atomicAdd(&gCnt[d4.z], 1);
        atomicAdd(&gCnt[d4.w], 1);
    }
    if (blockIdx.x == 0 && tid < (E & 3)) {
        atomicAdd(&gCnt[dst[(nquads << 2) + tid]], 1);
    }

    grid_barrier(gridDim.x);

    // ---- P1: lookback scan over gCnt (blocks 0..scanBlocks-1) ----
    const int scanBlocks = (N + 255) >> 8;
    if (blockIdx.x < scanBlocks) {
        const int bid = blockIdx.x;
        const int idx = bid * 256 + tid;

        int v = (idx < N) ? gCnt[idx] : 0;
        sh[tid] = v;
        __syncthreads();
#pragma unroll
        for (int o = 1; o < 256; o <<= 1) {
            int t = (tid >= o) ? sh[tid - o] : 0;
            __syncthreads();
            sh[tid] += t;
            __syncthreads();
        }
        const int incl = sh[tid];

        if (tid == 255) {
            gBlockSum[bid] = incl;
            __threadfence();
            gBlockFlag[bid] = 1;
        }
        int contrib = 0;
        if (tid < bid) {
            while (gBlockFlag[tid] == 0) { }
            contrib = gBlockSum[tid];
        }
        pre[tid] = contrib;
        __syncthreads();
        for (int o = 128; o > 0; o >>= 1) {
            if (tid < o) pre[tid] += pre[tid + o];
            __syncthreads();
        }
        const int excl = pre[0] + incl - v;
        if (idx < N) {
            gOff[idx]    = excl;
            gCursor[idx] = excl;
            if (idx == N - 1) gOff[N] = excl + v;   // == E
        }
    }

    grid_barrier(gridDim.x);

    // ---- P2: scatter into dst-grouped order, grid-stride, 4 edges/step ----
    for (int t = blockIdx.x * 256 + tid; t < nquads; t += gridDim.x * 256) {
        int4 s4 = reinterpret_cast<const int4*>(src)[t];
        int4 d4 = reinterpret_cast<const int4*>(dst)[t];
        const int e0 = t * 4;
        int p0 = atomicAdd(&gCursor[d4.x], 1);
        int p1 = atomicAdd(&gCursor[d4.y], 1);
        int p2 = atomicAdd(&gCursor[d4.z], 1);
        int p3 = atomicAdd(&gCursor[d4.w], 1);
        gSortedE[p0] = make_int2(s4.x, e0);
        gSortedE[p1] = make_int2(s4.y, e0 + 1);
        gSortedE[p2] = make_int2(s4.z, e0 + 2);
        gSortedE[p3] = make_int2(s4.w, e0 + 3);
    }
    if (blockIdx.x == 0 && tid < (E & 3)) {
        const int e = (nquads << 2) + tid;
        int pos = atomicAdd(&gCursor[dst[e]], 1);
        gSortedE[pos] = make_int2(src[e], e);
    }
}

// ---------------------------------------------------------------------------
// Kernel 2: FUSED per-node kernel — warp per node, no atomics.
// 8 lanes/edge, contiguous addressing, record prefetch pipeline.
// Also SELF-CLEANS gCnt[node]=0 so the next run needs no memset.
// ---------------------------------------------------------------------------
__global__ void __launch_bounds__(256, 3) fused_node(
        const float* __restrict__ y,
        const float* __restrict__ w2,
        const float* __restrict__ b2,
        float* __restrict__ alpha_out,
        float* __restrict__ yhat, int N) {
    const int lane = threadIdx.x & 31;
    const int sub  = lane & 7;          // lane within 8-group
    const int g    = lane >> 3;         // subgroup 0..3
    const int node = blockIdx.x * (blockDim.x >> 5) + (threadIdx.x >> 5);
    if (node >= N) return;

    if (lane == 0) gCnt[node] = 0;      // self-clean for the next run

    const int start = gOff[node];
    const int end   = gOff[node + 1];

    const uint4* A4 = reinterpret_cast<const uint4*>(gA);  // 16 uint4 / row
    const uint4* B4 = reinterpret_cast<const uint4*>(gB);

    // B[node]: lane sub holds halves [8*sub, 8*sub+8) and [64+8*sub, ...+8)
    uint4 br0 = B4[node * 16 + sub];
    uint4 br1 = B4[node * 16 + 8 + sub];
    __half2 bh0[4], bh1[4];
    {
        const __half2* p0 = reinterpret_cast<const __half2*>(&br0);
        const __half2* p1 = reinterpret_cast<const __half2*>(&br1);
#pragma unroll
        for (int i = 0; i < 4; i++) { bh0[i] = p0[i]; bh1[i] = p1[i]; }
    }

    // w2 coefficients matching the halves above
    float w2a[8], w2b[8];
#pragma unroll
    for (int i = 0; i < 2; i++) {
        float4 ta = reinterpret_cast<const float4*>(w2)[sub * 2 + i];
        float4 tb = reinterpret_cast<const float4*>(w2)[16 + sub * 2 + i];
        w2a[4 * i] = ta.x; w2a[4 * i + 1] = ta.y; w2a[4 * i + 2] = ta.z; w2a[4 * i + 3] = ta.w;
        w2b[4 * i] = tb.x; w2b[4 * i + 1] = tb.y; w2b[4 * i + 2] = tb.z; w2b[4 * i + 3] = tb.w;
    }
    const float  b2v = __ldg(b2);
    const __half2 z2 = __float2half2_rn(0.0f);

    float denom_part = 0.0f;

    // prologue: records for the first batch
    int s0 = (start + g     < end) ? gSortedE[start + g].x     : 0;
    int s1 = (start + g + 4 < end) ? gSortedE[start + g + 4].x : 0;

    for (int base = start; base < end; base += 8) {
        const int e0 = base + g, e1 = base + g + 4;
        const bool v0 = e0 < end, v1 = e1 < end;

        // prefetch next batch's records (overlaps A-gather + compute below)
        const int n0 = e0 + 8, n1 = e1 + 8;
        const int sn0 = (n0 < end) ? gSortedE[n0].x : 0;
        const int sn1 = (n1 < end) ? gSortedE[n1].x : 0;

        // 4 independent, fully-coalesced gathers issued before any use
        uint4 a00 = A4[s0 * 16 + sub];
        uint4 a01 = A4[s0 * 16 + 8 + sub];
        uint4 a10 = A4[s1 * 16 + sub];
        uint4 a11 = A4[s1 * 16 + 8 + sub];

        float p0 = 0.0f, p1 = 0.0f;
        {
            const __half2* q0 = reinterpret_cast<const __half2*>(&a00);
            const __half2* q1 = reinterpret_cast<const __half2*>(&a01);
            const __half2* r0 = reinterpret_cast<const __half2*>(&a10);
            const __half2* r1 = reinterpret_cast<const __half2*>(&a11);
#pragma unroll
            for (int i = 0; i < 4; i++) {
                float2 f;
                f = __half22float2(__hmax2(__hadd2(q0[i], bh0[i]), z2));
                p0 = fmaf(f.x, w2a[2 * i], fmaf(f.y, w2a[2 * i + 1], p0));
                f = __half22float2(__hmax2(__hadd2(q1[i], bh1[i]), z2));
                p0 = fmaf(f.x, w2b[2 * i], fmaf(f.y, w2b[2 * i + 1], p0));
                f = __half22float2(__hmax2(__hadd2(r0[i], bh0[i]), z2));
                p1 = fmaf(f.x, w2a[2 * i], fmaf(f.y, w2a[2 * i + 1], p1));
                f = __half22float2(__hmax2(__hadd2(r1[i], bh1[i]), z2));
                p1 = fmaf(f.x, w2b[2 * i], fmaf(f.y, w2b[2 * i + 1], p1));
            }
        }
        // two interleaved 3-step subgroup reductions
#pragma unroll
        for (int o = 4; o > 0; o >>= 1) {
            p0 += __shfl_xor_sync(0xFFFFFFFFu, p0, o);
            p1 += __shfl_xor_sync(0xFFFFFFFFu, p1, o);
        }
        if (sub == 0) {
            if (v0) { float ev = __expf(p0 + b2v); gEsort[e0] = ev; denom_part += ev; }
            if (v1) { float ev = __expf(p1 + b2v); gEsort[e1] = ev; denom_part += ev; }
        }
        s0 = sn0; s1 = sn1;
    }

    // total denom over the warp (only sub==0 lanes carry partials)
#pragma unroll
    for (int o = 16; o > 0; o >>= 1)
        denom_part += __shfl_xor_sync(0xFFFFFFFFu, denom_part, o);
    const float inv = 1.0f / denom_part;

    // pass 2: alpha + weighted sum, coalesced over the node's segment
    float sum = 0.0f;
    for (int i = start + lane; i < end; i += 32) {
        int2  rec = gSortedE[i];
        float a   = gEsort[i] * inv;
        alpha_out[rec.y] = a;
        sum += __ldg(&y[rec.x]) * a;
    }
#pragma unroll
    for (int o = 16; o > 0; o >>= 1)
        sum += __shfl_xor_sync(0xFFFFFFFFu, sum, o);
    if (lane == 0) yhat[node] = sum;
}

// ---------------------------------------------------------------------------
extern "C" void kernel_launch(void* const* d_in, const int* in_sizes, int n_in,
                              void* d_out, int out_size) {
    const float* x  = (const float*)d_in[0];
    const float* y  = (const float*)d_in[1];
    const int*   ei = (const int*)  d_in[2];
    const float* w1 = (const float*)d_in[3];
    const float* b1 = (const float*)d_in[4];
    const float* w2 = (const float*)d_in[5];
    const float* b2 = (const float*)d_in[6];

    const int N = in_sizes[1];        // y has N elements
    const int E = in_sizes[2] / 2;    // edge_index is [2, E]

    float* yhat  = (float*)d_out;         // first N elements
    float* alpha = (float*)d_out + N;     // next E elements

    const int* src = ei;
    const int* dst = ei + E;

    const int Ptiles = (N + TR - 1) / TR;

    prep_kernel<<<PREP_BLOCKS, 256>>>(x, w1, b1, src, dst, N, E, Ptiles);
    fused_node<<<(N + 7) / 8, 256>>>(y, w2, b2, alpha, yhat, N);
}

// round 17
// speedup vs baseline: 1.5579x; 1.5579x over previous
#include <cuda_runtime.h>
#include <cuda_fp16.h>

// Problem constants (fixed by the dataset)
#define NMAX 50048
#define EMAX 1600000
#define WDIM 64
#define HDIM 128

// Scratch (allocation-free rule: __device__ globals)
__device__ __half gA[NMAX * HDIM];     // x @ w1[0:64,:]  + b1
__device__ __half gB[NMAX * HDIM];     // x @ w1[64:128,:]
__device__ int    gCnt[NMAX];          // per-dst edge count (self-cleaning:
                                       // zero at load; fused_node re-zeros)
__device__ int    gOff[NMAX + 1];      // exclusive prefix (bin starts)
__device__ int    gCursor[NMAX];       // scatter cursors
__device__ int2   gSortedE[EMAX];      // {src, orig_e} grouped by dst
__device__ float  gEsort[EMAX];        // exp(logit) in sorted order
// decoupled-lookback scan state (flags reset by hist blocks each call)
__device__ volatile int gBlockSum[256];
__device__ volatile int gBlockFlag[256];

#define TR 16
#define HIST_BLOCKS 1024

// ---------------------------------------------------------------------------
// Kernel 1 (combined): blocks [0, Pblocks) run the A/B precompute GEMM;
// blocks [Pblocks, Pblocks+HIST_BLOCKS) run the dst histogram concurrently.
// ---------------------------------------------------------------------------
__global__ void precompute_and_hist(const float* __restrict__ x,
                                    const float* __restrict__ w1,
                                    const float* __restrict__ b1,
                                    const int* __restrict__ dst,
                                    int N, int E, int Pblocks) {
    if (blockIdx.x < Pblocks) {
        // ---- precompute role ----
        __shared__ float xs[TR][WDIM];
        const int row0 = blockIdx.x * TR;
        const int tid  = threadIdx.x;

        for (int i = tid; i < TR * WDIM; i += 256) {
            int r = i >> 6, k = i & 63;
            int gr = row0 + r;
            xs[r][k] = (gr < N) ? x[gr * WDIM + k] : 0.0f;
        }
        __syncthreads();

        const int col  = tid & 127;
        const int half = tid >> 7;   // 0 -> A, 1 -> B
        const float* wbase = w1 + half * WDIM * HDIM + col;

        float acc[TR];
#pragma unroll
        for (int r = 0; r < TR; r++) acc[r] = 0.0f;

#pragma unroll 8
        for (int k = 0; k < WDIM; k++) {
            float w = __ldg(wbase + k * HDIM);
#pragma unroll
            for (int r = 0; r < TR; r++) acc[r] += xs[r][k] * w;
        }

        const float bias = (half == 0) ? __ldg(&b1[col]) : 0.0f;
        __half* out = (half == 0) ? gA : gB;
#pragma unroll
        for (int r = 0; r < TR; r++) {
            int gr = row0 + r;
            if (gr < N) out[gr * HDIM + col] = __float2half_rn(acc[r] + bias);
        }
    } else {
        // ---- histogram role (grid-stride, 4 edges per thread step) ----
        const int hb = blockIdx.x - Pblocks;
        if (hb == 0 && threadIdx.x < 256) gBlockFlag[threadIdx.x] = 0;

        const int nquads  = E >> 2;                  // full int4 groups
        const int hstride = HIST_BLOCKS * 256;
        for (int t = hb * 256 + threadIdx.x; t < nquads; t += hstride) {
            int4 d4 = reinterpret_cast<const int4*>(dst)[t];
            atomicAdd(&gCnt[d4.x], 1);
            atomicAdd(&gCnt[d4.y], 1);
            atomicAdd(&gCnt[d4.z], 1);
            atomicAdd(&gCnt[d4.w], 1);
        }
        if (hb == 0 && threadIdx.x < (E & 3)) {
            atomicAdd(&gCnt[dst[(nquads << 2) + threadIdx.x]], 1);
        }
    }
}

// ---------------------------------------------------------------------------
// Kernel 2: single-pass scan, parallel lookback. 196 blocks, co-resident.
// ---------------------------------------------------------------------------
__global__ void scan_onepass(int N, int E) {
    __shared__ int sh[256];
    __shared__ int pre[256];
    const int bid = blockIdx.x;
    const int tid = threadIdx.x;
    const int idx = bid * 256 + tid;

    int v = (idx < N) ? gCnt[idx] : 0;
    sh[tid] = v;
    __syncthreads();
#pragma unroll
    for (int o = 1; o < 256; o <<= 1) {
        int t = (tid >= o) ? sh[tid - o] : 0;
        __syncthreads();
        sh[tid] += t;
        __syncthreads();
    }
    const int incl = sh[tid];          // inclusive within block

    if (tid == 255) {                  // publish block aggregate
        gBlockSum[bid] = incl;
        __threadfence();
        gBlockFlag[bid] = 1;
    }
    // parallel lookback: lane t grabs predecessor t's aggregate
    int contrib = 0;
    if (tid < bid) {
        while (gBlockFlag[tid] == 0) { }
        contrib = gBlockSum[tid];
    }
    pre[tid] = contrib;
    __syncthreads();
    for (int o = 128; o > 0; o >>= 1) {
        if (tid < o) pre[tid] += pre[tid + o];
        __syncthreads();
    }
    const int excl = pre[0] + incl - v;
    if (idx < N) {
        gOff[idx]    = excl;
        gCursor[idx] = excl;
        if (idx == N - 1) gOff[N] = excl + v;   // == E
    }
}

// ---------------------------------------------------------------------------
// Kernel 3: scatter edges into dst-grouped order (4 edges/thread)
// ---------------------------------------------------------------------------
__global__ void scatter_kernel(const int* __restrict__ src,
                               const int* __restrict__ dst, int E) {
    int t = blockIdx.x * blockDim.x + threadIdx.x;
    int e0 = t * 4;
    if (e0 + 3 < E) {
        int4 s4 = reinterpret_cast<const int4*>(src)[t];
        int4 d4 = reinterpret_cast<const int4*>(dst)[t];
        int p0 = atomicAdd(&gCursor[d4.x], 1);
        int p1 = atomicAdd(&gCursor[d4.y], 1);
        int p2 = atomicAdd(&gCursor[d4.z], 1);
        int p3 = atomicAdd(&gCursor[d4.w], 1);
        gSortedE[p0] = make_int2(s4.x, e0);
        gSortedE[p1] = make_int2(s4.y, e0 + 1);
        gSortedE[p2] = make_int2(s4.z, e0 + 2);
        gSortedE[p3] = make_int2(s4.w, e0 + 3);
    } else {
        for (int e = e0; e < E; e++) {
            int pos = atomicAdd(&gCursor[dst[e]], 1);
            gSortedE[pos] = make_int2(src[e], e);
        }
    }
}

// ---------------------------------------------------------------------------
// Kernel 4: FUSED per-node kernel — warp per node, no atomics.
// 8 lanes/edge, contiguous addressing, record prefetch pipeline.
// regs fit 64 -> allow 4 blocks/SM (was capped at 3): issue-bound kernel
// gains eligible warps (occ 41% -> ~55%).
// Also SELF-CLEANS gCnt[node]=0 so the next run needs no memset.
// ---------------------------------------------------------------------------
__global__ void __launch_bounds__(256, 4) fused_node(
        const float* __restrict__ y,
        const float* __restrict__ w2,
        const float* __restrict__ b2,
        float* __restrict__ alpha_out,
        float* __restrict__ yhat, int N) {
    const int lane = threadIdx.x & 31;
    const int sub  = lane & 7;          // lane within 8-group
    const int g    = lane >> 3;         // subgroup 0..3
    const int node = blockIdx.x * (blockDim.x >> 5) + (threadIdx.x >> 5);
    if (node >= N) return;

    if (lane == 0) gCnt[node] = 0;      // self-clean for the next run

    const int start = gOff[node];
    const int end   = gOff[node + 1];

    const uint4* A4 = reinterpret_cast<const uint4*>(gA);  // 16 uint4 / row
    const uint4* B4 = reinterpret_cast<const uint4*>(gB);

    // B[node]: lane sub holds halves [8*sub, 8*sub+8) and [64+8*sub, ...+8)
    uint4 br0 = B4[node * 16 + sub];
    uint4 br1 = B4[node * 16 + 8 + sub];
    __half2 bh0[4], bh1[4];
    {
        const __half2* p0 = reinterpret_cast<const __half2*>(&br0);
        const __half2* p1 = reinterpret_cast<const __half2*>(&br1);
#pragma unroll
        for (int i = 0; i < 4; i++) { bh0[i] = p0[i]; bh1[i] = p1[i]; }
    }

    // w2 coefficients matching the halves above
    float w2a[8], w2b[8];
#pragma unroll
    for (int i = 0; i < 2; i++) {
        float4 ta = reinterpret_cast<const float4*>(w2)[sub * 2 + i];
        float4 tb = reinterpret_cast<const float4*>(w2)[16 + sub * 2 + i];
        w2a[4 * i] = ta.x; w2a[4 * i + 1] = ta.y; w2a[4 * i + 2] = ta.z; w2a[4 * i + 3] = ta.w;
        w2b[4 * i] = tb.x; w2b[4 * i + 1] = tb.y; w2b[4 * i + 2] = tb.z; w2b[4 * i + 3] = tb.w;
    }
    const float  b2v = __ldg(b2);
    const __half2 z2 = __float2half2_rn(0.0f);

    float denom_part = 0.0f;

    // prologue: records for the first batch
    int s0 = (start + g     < end) ? gSortedE[start + g].x     : 0;
    int s1 = (start + g + 4 < end) ? gSortedE[start + g + 4].x : 0;

    for (int base = start; base < end; base += 8) {
        const int e0 = base + g, e1 = base + g + 4;
        const bool v0 = e0 < end, v1 = e1 < end;

        // prefetch next batch's records (overlaps A-gather + compute below)
        const int n0 = e0 + 8, n1 = e1 + 8;
        const int sn0 = (n0 < end) ? gSortedE[n0].x : 0;
        const int sn1 = (n1 < end) ? gSortedE[n1].x : 0;

        // 4 independent, fully-coalesced gathers issued before any use
        uint4 a00 = A4[s0 * 16 + sub];
        uint4 a01 = A4[s0 * 16 + 8 + sub];
        uint4 a10 = A4[s1 * 16 + sub];
        uint4 a11 = A4[s1 * 16 + 8 + sub];

        float p0 = 0.0f, p1 = 0.0f;
        {
            const __half2* q0 = reinterpret_cast<const __half2*>(&a00);
            const __half2* q1 = reinterpret_cast<const __half2*>(&a01);
            const __half2* r0 = reinterpret_cast<const __half2*>(&a10);
            const __half2* r1 = reinterpret_cast<const __half2*>(&a11);
#pragma unroll
            for (int i = 0; i < 4; i++) {
                float2 f;
                f = __half22float2(__hmax2(__hadd2(q0[i], bh0[i]), z2));
                p0 = fmaf(f.x, w2a[2 * i], fmaf(f.y, w2a[2 * i + 1], p0));
                f = __half22float2(__hmax2(__hadd2(q1[i], bh1[i]), z2));
                p0 = fmaf(f.x, w2b[2 * i], fmaf(f.y, w2b[2 * i + 1], p0));
                f = __half22float2(__hmax2(__hadd2(r0[i], bh0[i]), z2));
                p1 = fmaf(f.x, w2a[2 * i], fmaf(f.y, w2a[2 * i + 1], p1));
                f = __half22float2(__hmax2(__hadd2(r1[i], bh1[i]), z2));
                p1 = fmaf(f.x, w2b[2 * i], fmaf(f.y, w2b[2 * i + 1], p1));
            }
        }
        // two interleaved 3-step subgroup reductions
#pragma unroll
        for (int o = 4; o > 0; o >>= 1) {
            p0 += __shfl_xor_sync(0xFFFFFFFFu, p0, o);
            p1 += __shfl_xor_sync(0xFFFFFFFFu, p1, o);
        }
        if (sub == 0) {
            if (v0) { float ev = __expf(p0 + b2v); gEsort[e0] = ev; denom_part += ev; }
            if (v1) { float ev = __expf(p1 + b2v); gEsort[e1] = ev; denom_part += ev; }
        }
        s0 = sn0; s1 = sn1;
    }

    // total denom over the warp (only sub==0 lanes carry partials)
#pragma unroll
    for (int o = 16; o > 0; o >>= 1)
        denom_part += __shfl_xor_sync(0xFFFFFFFFu, denom_part, o);
    const float inv = 1.0f / denom_part;

    // pass 2: alpha + weighted sum, coalesced over the node's segment
    float sum = 0.0f;
    for (int i = start + lane; i < end; i += 32) {
        int2  rec = gSortedE[i];
        float a   = gEsort[i] * inv;
        alpha_out[rec.y] = a;
        sum += __ldg(&y[rec.x]) * a;
    }
#pragma unroll
    for (int o = 16; o > 0; o >>= 1)
        sum += __shfl_xor_sync(0xFFFFFFFFu, sum, o);
    if (lane == 0) yhat[node] = sum;
}

// ---------------------------------------------------------------------------
extern "C" void kernel_launch(void* const* d_in, const int* in_sizes, int n_in,
                              void* d_out, int out_size) {
    const float* x  = (const float*)d_in[0];
    const float* y  = (const float*)d_in[1];
    const int*   ei = (const int*)  d_in[2];
    const float* w1 = (const float*)d_in[3];
    const float* b1 = (const float*)d_in[4];
    const float* w2 = (const float*)d_in[5];
    const float* b2 = (const float*)d_in[6];

    const int N = in_sizes[1];        // y has N elements
    const int E = in_sizes[2] / 2;    // edge_index is [2, E]

    float* yhat  = (float*)d_out;         // first N elements
    float* alpha = (float*)d_out + N;     // next E elements

    const int* src = ei;
    const int* dst = ei + E;

    const int Pblocks    = (N + TR - 1) / TR;   // precompute blocks
    const int scanBlocks = (N + 255) / 256;     // 196 <= 256

    precompute_and_hist<<<Pblocks + HIST_BLOCKS, 256>>>(x, w1, b1, dst,
                                                        N, E, Pblocks);
    scan_onepass<<<scanBlocks, 256>>>(N, E);
    scatter_kernel<<<(E / 4 + 255) / 256, 256>>>(src, dst, E);
    fused_node<<<(N + 7) / 8, 256>>>(y, w2, b2, alpha, yhat, N);
}